// round 1
// baseline (speedup 1.0000x reference)
#include <cuda_runtime.h>
#include <math.h>

// Problem constants
#define NT   2048            // tokens (B*S)
#define DIM  2048            // hidden
#define FFN_ 768             // ffn dim
#define NE   64              // experts
#define TOPK 8
#define NP   (NT*TOPK)       // 16384 routed pairs
#define CAP  512             // per-expert capacity (2 * NP / NE)

// ---------------- scratch (device globals; no allocation allowed) ----------
__device__ int   g_cnt[NE];
__device__ int   g_tok[NE*CAP];          // token per (expert, slot)
__device__ int   g_eid[NP];              // expert id per pair
__device__ int   g_slot[NP];             // slot per pair
__device__ float g_scr[NP];              // softmax score per pair
__device__ float g_h[(size_t)NE*CAP*FFN_];     // ~100 MB  silu(g)*u
__device__ float g_y[(size_t)NE*CAP*DIM];      // ~268 MB  expert outputs

// ---------------- K1: gating logits + softmax + top-8 ---------------------
// 4 tokens per block, 256 threads (8 warps). Each warp computes 32 of the
// 4*64 = 256 dot products (warp-strided over DIM, warp reduce).
__global__ __launch_bounds__(256) void k_gate(const float* __restrict__ x,
                                              const float* __restrict__ gw) {
    __shared__ float sx[4][DIM];
    __shared__ float slog[4][NE];
    const int t0  = blockIdx.x * 4;
    const int tid = threadIdx.x;

    // load 4 token rows (float4)
    for (int i = tid; i < 4 * (DIM / 4); i += 256) {
        int row = i / (DIM / 4);
        int c   = i % (DIM / 4);
        ((float4*)sx[row])[c] = ((const float4*)(x + (size_t)(t0 + row) * DIM))[c];
    }
    __syncthreads();

    const int warp = tid >> 5, lane = tid & 31;
    for (int d = warp * 32; d < warp * 32 + 32; d++) {
        int tk = d >> 6;            // 0..3
        int e  = d & 63;            // 0..63
        const float* w = gw + (size_t)e * DIM;
        float acc = 0.f;
        for (int i = lane * 4; i < DIM; i += 128) {
            float4 xv = *(const float4*)&sx[tk][i];
            float4 wv = *(const float4*)&w[i];
            acc += xv.x * wv.x + xv.y * wv.y + xv.z * wv.z + xv.w * wv.w;
        }
        #pragma unroll
        for (int o = 16; o; o >>= 1) acc += __shfl_xor_sync(0xffffffffu, acc, o);
        if (lane == 0) slog[tk][e] = acc;
    }
    __syncthreads();

    if (tid < 4) {
        const int tk = tid, token = t0 + tk;
        float m = -1e30f;
        for (int e = 0; e < NE; e++) m = fmaxf(m, slog[tk][e]);
        float pr[NE];
        float s = 0.f;
        for (int e = 0; e < NE; e++) { pr[e] = __expf(slog[tk][e] - m); s += pr[e]; }
        const float inv = 1.f / s;
        for (int k = 0; k < TOPK; k++) {
            float best = -1.f; int be = 0;
            for (int e = 0; e < NE; e++) if (pr[e] > best) { best = pr[e]; be = e; }
            g_eid[token * TOPK + k] = be;
            g_scr[token * TOPK + k] = best * inv;
            pr[be] = -2.f;
        }
    }
}

// ---------------- K2: routing -----------------------------------------------
__global__ void k_zero() { if (threadIdx.x < NE) g_cnt[threadIdx.x] = 0; }

__global__ void k_route() {
    int p = blockIdx.x * 256 + threadIdx.x;
    if (p >= NP) return;
    int e = g_eid[p];
    int slot = atomicAdd(&g_cnt[e], 1);
    g_slot[p] = slot;
    if (slot < CAP) g_tok[e * CAP + slot] = p >> 3;   // token index
}

// ---------------- K3: fused gate/up GEMM + SwiGLU ---------------------------
// Per block: expert e, 64 rows x 64 ffn cols, K = DIM in chunks of 32.
// h[m][n] = silu(X.Wg^T) * (X.Wu^T)
__global__ __launch_bounds__(256) void k_gateup(const float* __restrict__ x,
                                                const float* __restrict__ wg,
                                                const float* __restrict__ wu) {
    const int e = blockIdx.z;
    int nrows = g_cnt[e]; if (nrows > CAP) nrows = CAP;
    const int row0 = blockIdx.y * 64;
    if (row0 >= nrows) return;
    const int f0 = blockIdx.x * 64;

    __shared__ float Xs[32][68];
    __shared__ float Gs[32][68];
    __shared__ float Us[32][68];

    const int tid = threadIdx.x;
    const int m_a = tid >> 3;          // 0..31
    const int kva = tid & 7;           // 0..7 -> k = kva*4
    const int kk  = kva * 4;

    int tokA = -1, tokB = -1;
    { int r = row0 + m_a;      if (r < nrows) tokA = g_tok[e * CAP + r];
      r = row0 + m_a + 32;     if (r < nrows) tokB = g_tok[e * CAP + r]; }

    const float* wgp = wg + ((size_t)e * FFN_ + f0) * DIM;
    const float* wup = wu + ((size_t)e * FFN_ + f0) * DIM;

    const int tx = tid & 15, ty = tid >> 4;
    float accg[16], accu[16];
    #pragma unroll
    for (int i = 0; i < 16; i++) { accg[i] = 0.f; accu[i] = 0.f; }

    for (int kt = 0; kt < DIM / 32; kt++) {
        const int k0 = kt * 32;
        __syncthreads();
        // X gather (rows m_a, m_a+32)
        {
            float4 v = make_float4(0.f, 0.f, 0.f, 0.f);
            if (tokA >= 0) v = *(const float4*)&x[(size_t)tokA * DIM + k0 + kk];
            Xs[kk][m_a] = v.x; Xs[kk+1][m_a] = v.y; Xs[kk+2][m_a] = v.z; Xs[kk+3][m_a] = v.w;
            float4 v2 = make_float4(0.f, 0.f, 0.f, 0.f);
            if (tokB >= 0) v2 = *(const float4*)&x[(size_t)tokB * DIM + k0 + kk];
            Xs[kk][m_a+32] = v2.x; Xs[kk+1][m_a+32] = v2.y; Xs[kk+2][m_a+32] = v2.z; Xs[kk+3][m_a+32] = v2.w;
        }
        // weights (rows f0+m_a, f0+m_a+32)
        {
            float4 a = *(const float4*)&wgp[(size_t)m_a * DIM + k0 + kk];
            Gs[kk][m_a] = a.x; Gs[kk+1][m_a] = a.y; Gs[kk+2][m_a] = a.z; Gs[kk+3][m_a] = a.w;
            float4 b = *(const float4*)&wgp[(size_t)(m_a+32) * DIM + k0 + kk];
            Gs[kk][m_a+32] = b.x; Gs[kk+1][m_a+32] = b.y; Gs[kk+2][m_a+32] = b.z; Gs[kk+3][m_a+32] = b.w;
            float4 c = *(const float4*)&wup[(size_t)m_a * DIM + k0 + kk];
            Us[kk][m_a] = c.x; Us[kk+1][m_a] = c.y; Us[kk+2][m_a] = c.z; Us[kk+3][m_a] = c.w;
            float4 d = *(const float4*)&wup[(size_t)(m_a+32) * DIM + k0 + kk];
            Us[kk][m_a+32] = d.x; Us[kk+1][m_a+32] = d.y; Us[kk+2][m_a+32] = d.z; Us[kk+3][m_a+32] = d.w;
        }
        __syncthreads();

        #pragma unroll
        for (int k = 0; k < 32; k++) {
            float4 a  = *(const float4*)&Xs[k][ty * 4];
            float4 bg = *(const float4*)&Gs[k][tx * 4];
            float4 bu = *(const float4*)&Us[k][tx * 4];
            float av[4] = {a.x, a.y, a.z, a.w};
            float gv[4] = {bg.x, bg.y, bg.z, bg.w};
            float uv[4] = {bu.x, bu.y, bu.z, bu.w};
            #pragma unroll
            for (int i = 0; i < 4; i++)
                #pragma unroll
                for (int j = 0; j < 4; j++) {
                    accg[i*4+j] += av[i] * gv[j];
                    accu[i*4+j] += av[i] * uv[j];
                }
        }
    }

    // epilogue: silu(g)*u
    #pragma unroll
    for (int i = 0; i < 4; i++) {
        int m = row0 + ty * 4 + i;
        if (m >= nrows) continue;
        float* hp = &g_h[((size_t)e * CAP + m) * FFN_ + f0 + tx * 4];
        #pragma unroll
        for (int j = 0; j < 4; j++) {
            float g = accg[i*4+j];
            float u = accu[i*4+j];
            hp[j] = (g / (1.f + __expf(-g))) * u;
        }
    }
}

// ---------------- K4: down GEMM ---------------------------------------------
// y[m][d] = sum_f h[m][f] * wd[d][f]
__global__ __launch_bounds__(256) void k_down(const float* __restrict__ wd) {
    const int e = blockIdx.z;
    int nrows = g_cnt[e]; if (nrows > CAP) nrows = CAP;
    const int row0 = blockIdx.y * 64;
    if (row0 >= nrows) return;
    const int d0 = blockIdx.x * 64;

    __shared__ float Hs[32][68];
    __shared__ float Ws[32][68];

    const int tid = threadIdx.x;
    const int m_a = tid >> 3;
    const int kk  = (tid & 7) * 4;

    const bool vA = (row0 + m_a) < nrows;
    const bool vB = (row0 + m_a + 32) < nrows;
    const float* hpA = &g_h[((size_t)e * CAP + row0 + m_a) * FFN_];
    const float* hpB = &g_h[((size_t)e * CAP + row0 + m_a + 32) * FFN_];
    const float* wdp = wd + ((size_t)e * DIM + d0) * FFN_;

    const int tx = tid & 15, ty = tid >> 4;
    float acc[16];
    #pragma unroll
    for (int i = 0; i < 16; i++) acc[i] = 0.f;

    for (int kt = 0; kt < FFN_ / 32; kt++) {
        const int k0 = kt * 32;
        __syncthreads();
        {
            float4 v = make_float4(0.f, 0.f, 0.f, 0.f);
            if (vA) v = *(const float4*)&hpA[k0 + kk];
            Hs[kk][m_a] = v.x; Hs[kk+1][m_a] = v.y; Hs[kk+2][m_a] = v.z; Hs[kk+3][m_a] = v.w;
            float4 v2 = make_float4(0.f, 0.f, 0.f, 0.f);
            if (vB) v2 = *(const float4*)&hpB[k0 + kk];
            Hs[kk][m_a+32] = v2.x; Hs[kk+1][m_a+32] = v2.y; Hs[kk+2][m_a+32] = v2.z; Hs[kk+3][m_a+32] = v2.w;

            float4 a = *(const float4*)&wdp[(size_t)m_a * FFN_ + k0 + kk];
            Ws[kk][m_a] = a.x; Ws[kk+1][m_a] = a.y; Ws[kk+2][m_a] = a.z; Ws[kk+3][m_a] = a.w;
            float4 b = *(const float4*)&wdp[(size_t)(m_a+32) * FFN_ + k0 + kk];
            Ws[kk][m_a+32] = b.x; Ws[kk+1][m_a+32] = b.y; Ws[kk+2][m_a+32] = b.z; Ws[kk+3][m_a+32] = b.w;
        }
        __syncthreads();

        #pragma unroll
        for (int k = 0; k < 32; k++) {
            float4 a = *(const float4*)&Hs[k][ty * 4];
            float4 b = *(const float4*)&Ws[k][tx * 4];
            float av[4] = {a.x, a.y, a.z, a.w};
            float bv[4] = {b.x, b.y, b.z, b.w};
            #pragma unroll
            for (int i = 0; i < 4; i++)
                #pragma unroll
                for (int j = 0; j < 4; j++)
                    acc[i*4+j] += av[i] * bv[j];
        }
    }

    #pragma unroll
    for (int i = 0; i < 4; i++) {
        int m = row0 + ty * 4 + i;
        if (m >= nrows) continue;
        float* yp = &g_y[((size_t)e * CAP + m) * DIM + d0 + tx * 4];
        #pragma unroll
        for (int j = 0; j < 4; j++) yp[j] = acc[i*4+j];
    }
}

// ---------------- K5: weighted combine --------------------------------------
__global__ __launch_bounds__(256) void k_combine(float* __restrict__ out) {
    const int t = blockIdx.x;
    const int tid = threadIdx.x;
    float4 acc0 = make_float4(0.f, 0.f, 0.f, 0.f);
    float4 acc1 = make_float4(0.f, 0.f, 0.f, 0.f);
    #pragma unroll
    for (int k = 0; k < TOPK; k++) {
        const int p = t * TOPK + k;
        const int e = g_eid[p];
        const int s = g_slot[p];
        if (s >= CAP) continue;            // capacity drop (matches reference)
        const float sc = g_scr[p];
        const float4* yr = (const float4*)&g_y[((size_t)e * CAP + s) * DIM];
        float4 v0 = yr[tid];
        float4 v1 = yr[tid + 256];
        acc0.x += sc * v0.x; acc0.y += sc * v0.y; acc0.z += sc * v0.z; acc0.w += sc * v0.w;
        acc1.x += sc * v1.x; acc1.y += sc * v1.y; acc1.z += sc * v1.z; acc1.w += sc * v1.w;
    }
    float4* op = (float4*)(out + (size_t)t * DIM);
    op[tid] = acc0;
    op[tid + 256] = acc1;
}

// ---------------- launch -----------------------------------------------------
extern "C" void kernel_launch(void* const* d_in, const int* in_sizes, int n_in,
                              void* d_out, int out_size) {
    (void)in_sizes; (void)n_in; (void)out_size;
    const float* x      = (const float*)d_in[0];   // [1, 2048, 2048]
    const float* gate_w = (const float*)d_in[1];   // [64, 2048]
    const float* w_gate = (const float*)d_in[2];   // [64, 768, 2048]
    const float* w_up   = (const float*)d_in[3];   // [64, 768, 2048]
    const float* w_down = (const float*)d_in[4];   // [64, 2048, 768]
    float* out          = (float*)d_out;           // [1, 2048, 2048]

    k_gate<<<NT / 4, 256>>>(x, gate_w);
    k_zero<<<1, 64>>>();
    k_route<<<NP / 256, 256>>>();
    k_gateup<<<dim3(FFN_ / 64, CAP / 64, NE), 256>>>(x, w_gate, w_up);
    k_down<<<dim3(DIM / 64, CAP / 64, NE), 256>>>(w_down);
    k_combine<<<NT, 256>>>(out);
}

// round 6
// speedup vs baseline: 4.9392x; 4.9392x over previous
#include <cuda_runtime.h>
#include <cuda_fp16.h>
#include <cstdint>
#include <math.h>

#define NT   2048
#define DIM  2048
#define FFN_ 768
#define NE   64
#define TOPK 8
#define NP   (NT*TOPK)
#define CAP  512

// ---------------- scratch ----------------------------------------------------
__device__ int    g_cnt[NE];
__device__ int    g_tok[NE*CAP];
__device__ int    g_eid[NP];
__device__ int    g_slot[NP];
__device__ float  g_scr[NP];
__device__ __half g_h[(size_t)NE*CAP*FFN_];   // 50 MB, fp16 activations
__device__ float  g_y[(size_t)NE*CAP*DIM];    // 268 MB

// ---------------- helpers ----------------------------------------------------
__device__ __forceinline__ uint32_t smem_u32(const void* p) {
    uint32_t a;
    asm("{ .reg .u64 t; cvta.to.shared.u64 t, %1; cvt.u32.u64 %0, t; }" : "=r"(a) : "l"(p));
    return a;
}
__device__ __forceinline__ void ldsm4(uint32_t* r, uint32_t addr) {
    asm volatile("ldmatrix.sync.aligned.m8n8.x4.shared.b16 {%0,%1,%2,%3}, [%4];"
                 : "=r"(r[0]), "=r"(r[1]), "=r"(r[2]), "=r"(r[3]) : "r"(addr));
}
__device__ __forceinline__ void mma16816(float* d, const uint32_t* a, const uint32_t* b) {
    asm volatile("mma.sync.aligned.m16n8k16.row.col.f32.f16.f16.f32 "
                 "{%0,%1,%2,%3}, {%4,%5,%6,%7}, {%8,%9}, {%0,%1,%2,%3};"
                 : "+f"(d[0]), "+f"(d[1]), "+f"(d[2]), "+f"(d[3])
                 : "r"(a[0]), "r"(a[1]), "r"(a[2]), "r"(a[3]), "r"(b[0]), "r"(b[1]));
}
__device__ __forceinline__ uint32_t pack2(float a, float b) {
    __half2 h = __floats2half2_rn(a, b);
    return *reinterpret_cast<uint32_t*>(&h);
}
__device__ __forceinline__ float silu_(float g) { return g / (1.f + __expf(-g)); }

// ---------------- K1: gating (fp32 exact) ------------------------------------
__global__ __launch_bounds__(256) void k_gate(const float* __restrict__ x,
                                              const float* __restrict__ gw) {
    __shared__ float sx[4][DIM];
    __shared__ float slog[4][NE];
    const int t0 = blockIdx.x * 4;
    const int tid = threadIdx.x;
    for (int i = tid; i < 4 * (DIM / 4); i += 256) {
        int row = i / (DIM / 4), c = i % (DIM / 4);
        ((float4*)sx[row])[c] = ((const float4*)(x + (size_t)(t0 + row) * DIM))[c];
    }
    __syncthreads();
    const int warp = tid >> 5, lane = tid & 31;
    for (int d = warp * 32; d < warp * 32 + 32; d++) {
        int tk = d >> 6, e = d & 63;
        const float* w = gw + (size_t)e * DIM;
        float acc = 0.f;
        for (int i = lane * 4; i < DIM; i += 128) {
            float4 xv = *(const float4*)&sx[tk][i];
            float4 wv = *(const float4*)&w[i];
            acc += xv.x * wv.x + xv.y * wv.y + xv.z * wv.z + xv.w * wv.w;
        }
        #pragma unroll
        for (int o = 16; o; o >>= 1) acc += __shfl_xor_sync(0xffffffffu, acc, o);
        if (lane == 0) slog[tk][e] = acc;
    }
    __syncthreads();
    if (tid < 4) {
        const int tk = tid, token = t0 + tk;
        float m = -1e30f;
        for (int e = 0; e < NE; e++) m = fmaxf(m, slog[tk][e]);
        float pr[NE], s = 0.f;
        for (int e = 0; e < NE; e++) { pr[e] = __expf(slog[tk][e] - m); s += pr[e]; }
        const float inv = 1.f / s;
        for (int k = 0; k < TOPK; k++) {
            float best = -1.f; int be = 0;
            for (int e = 0; e < NE; e++) if (pr[e] > best) { best = pr[e]; be = e; }
            g_eid[token * TOPK + k] = be;
            g_scr[token * TOPK + k] = best * inv;
            pr[be] = -2.f;
        }
    }
}

// ---------------- K2: routing ------------------------------------------------
__global__ void k_zero() { if (threadIdx.x < NE) g_cnt[threadIdx.x] = 0; }
__global__ void k_route() {
    int p = blockIdx.x * 256 + threadIdx.x;
    if (p >= NP) return;
    int e = g_eid[p];
    int slot = atomicAdd(&g_cnt[e], 1);
    g_slot[p] = slot;
    if (slot < CAP) g_tok[e * CAP + slot] = p >> 3;
}

// ---------------- K3: gate/up GEMM (fp16 mma) + SwiGLU -----------------------
// CTA tile: M=128 rows x N=128 cols (n-tiles of 8 interleaved gate/up over a
// 64-wide ffn slab), K = DIM in chunks of 64. 8 warps: warp_m in {0,1}(x64),
// warp_n in {0..3}(x32). Each warp: 4 m-tiles(16) x 4 n-tiles(8).
__global__ __launch_bounds__(256, 1) void k_gateup_mma(const float* __restrict__ x,
                                                       const float* __restrict__ wg,
                                                       const float* __restrict__ wu) {
    __shared__ __align__(1024) uint8_t sm[32768];   // A 16KB | B 16KB
    const int e = blockIdx.z;
    int nrows = g_cnt[e]; if (nrows > CAP) nrows = CAP;
    const int row0 = blockIdx.y * 128;
    if (row0 >= nrows) return;
    const int f0 = blockIdx.x * 64;

    const int tid = threadIdx.x;
    const int wid = tid >> 5, lane = tid & 31;
    const int wm = wid & 1, wn = wid >> 1;
    const uint32_t sA = smem_u32(sm);
    const uint32_t sB = sA + 16384;

    // load/convert mapping: thread (lrow=tid/16, lcol=tid%16); 8 iters cover 128 rows
    const int lrow = tid >> 4, lcol = tid & 15;
    const float* asrc[8]; const float* bsrc[8];
    uint32_t offa[8], offb[8];
    #pragma unroll
    for (int i = 0; i < 8; i++) {
        int r = i * 16 + lrow;
        int rr = row0 + r;
        int tok = g_tok[e * CAP + (rr < nrows ? rr : 0)];
        asrc[i] = x + (size_t)tok * DIM + lcol * 4;
        // B row r -> n-tile t8; even tiles = gate, odd = up, sharing f-block t8/2
        int t8 = r >> 3, w8 = r & 7;
        int fr = f0 + (t8 >> 1) * 8 + w8;
        const float* wb = (t8 & 1) ? wu : wg;
        bsrc[i] = wb + ((size_t)e * FFN_ + fr) * DIM + lcol * 4;
        uint32_t c = (uint32_t)(lcol * 8);
        offa[i] = r * 128 + (c ^ ((r & 7) << 4));
        offb[i] = offa[i] + 16384;
    }

    float acc[4][4][4];
    #pragma unroll
    for (int a = 0; a < 4; a++)
        #pragma unroll
        for (int b = 0; b < 4; b++)
            #pragma unroll
            for (int c = 0; c < 4; c++) acc[a][b][c] = 0.f;

    float4 va[8], vb[8];
    #pragma unroll
    for (int i = 0; i < 8; i++) { va[i] = *(const float4*)asrc[i]; vb[i] = *(const float4*)bsrc[i]; }

    const int NKC = DIM / 64;     // 32
    #pragma unroll 1
    for (int j = 0; j < NKC; j++) {
        __syncthreads();
        #pragma unroll
        for (int i = 0; i < 8; i++) {
            uint2 pa; pa.x = pack2(va[i].x, va[i].y); pa.y = pack2(va[i].z, va[i].w);
            *(uint2*)(sm + offa[i]) = pa;
            uint2 pb; pb.x = pack2(vb[i].x, vb[i].y); pb.y = pack2(vb[i].z, vb[i].w);
            *(uint2*)(sm + offb[i]) = pb;
        }
        __syncthreads();
        if (j + 1 < NKC) {
            #pragma unroll
            for (int i = 0; i < 8; i++) {
                va[i] = *(const float4*)(asrc[i] + (j + 1) * 64);
                vb[i] = *(const float4*)(bsrc[i] + (j + 1) * 64);
            }
        }
        #pragma unroll
        for (int ks = 0; ks < 4; ks++) {
            uint32_t af[4][4], bf[2][4];
            #pragma unroll
            for (int mt = 0; mt < 4; mt++) {
                int row = wm * 64 + mt * 16 + (lane & 15);
                int byt = ks * 32 + ((lane >> 4) << 4);
                ldsm4(af[mt], sA + row * 128 + (byt ^ ((row & 7) << 4)));
            }
            #pragma unroll
            for (int n2 = 0; n2 < 2; n2++) {
                int row = wn * 32 + n2 * 16 + ((lane >> 4) << 3) + (lane & 7);
                int byt = ks * 32 + (((lane >> 3) & 1) << 4);
                ldsm4(bf[n2], sB + row * 128 + (byt ^ ((row & 7) << 4)));
            }
            #pragma unroll
            for (int mt = 0; mt < 4; mt++)
                #pragma unroll
                for (int nt = 0; nt < 4; nt++)
                    mma16816(acc[mt][nt], af[mt], &bf[nt >> 1][(nt & 1) * 2]);
        }
    }

    // epilogue: n-tile pairs (2p=gate, 2p+1=up) -> h = silu(g)*u, fp16 store
    const int qrow = lane >> 2, qcol = (lane & 3) * 2;
    #pragma unroll
    for (int mt = 0; mt < 4; mt++) {
        int mbase = row0 + wm * 64 + mt * 16;
        #pragma unroll
        for (int p = 0; p < 2; p++) {
            int fbase = f0 + (wn * 2 + p) * 8 + qcol;
            float* gA = acc[mt][2 * p];
            float* uA = acc[mt][2 * p + 1];
            int r0 = mbase + qrow, r1 = mbase + qrow + 8;
            if (r0 < nrows) {
                __half2 h = __floats2half2_rn(silu_(gA[0]) * uA[0], silu_(gA[1]) * uA[1]);
                *(__half2*)&g_h[((size_t)e * CAP + r0) * FFN_ + fbase] = h;
            }
            if (r1 < nrows) {
                __half2 h = __floats2half2_rn(silu_(gA[2]) * uA[2], silu_(gA[3]) * uA[3]);
                *(__half2*)&g_h[((size_t)e * CAP + r1) * FFN_ + fbase] = h;
            }
        }
    }
}

// ---------------- K4: down GEMM (fp16 mma) -----------------------------------
__global__ __launch_bounds__(256, 1) void k_down_mma(const float* __restrict__ wd) {
    __shared__ __align__(1024) uint8_t sm[32768];
    const int e = blockIdx.z;
    int nrows = g_cnt[e]; if (nrows > CAP) nrows = CAP;
    const int row0 = blockIdx.y * 128;
    if (row0 >= nrows) return;
    const int d0 = blockIdx.x * 128;

    const int tid = threadIdx.x;
    const int wid = tid >> 5, lane = tid & 31;
    const int wm = wid & 1, wn = wid >> 1;
    const uint32_t sA = smem_u32(sm);
    const uint32_t sB = sA + 16384;

    const int lrow = tid >> 4, lcol = tid & 15;
    const __half* asrc[8]; const float* bsrc[8];
    uint32_t offa[8], offb[8];
    #pragma unroll
    for (int i = 0; i < 8; i++) {
        int r = i * 16 + lrow;
        asrc[i] = g_h + ((size_t)e * CAP + row0 + r) * FFN_ + lcol * 4;   // stale rows masked later
        bsrc[i] = wd + ((size_t)e * DIM + d0 + r) * FFN_ + lcol * 4;
        uint32_t c = (uint32_t)(lcol * 8);
        offa[i] = r * 128 + (c ^ ((r & 7) << 4));
        offb[i] = offa[i] + 16384;
    }

    float acc[4][4][4];
    #pragma unroll
    for (int a = 0; a < 4; a++)
        #pragma unroll
        for (int b = 0; b < 4; b++)
            #pragma unroll
            for (int c = 0; c < 4; c++) acc[a][b][c] = 0.f;

    uint2 va[8]; float4 vb[8];
    #pragma unroll
    for (int i = 0; i < 8; i++) { va[i] = *(const uint2*)asrc[i]; vb[i] = *(const float4*)bsrc[i]; }

    const int NKC = FFN_ / 64;    // 12
    #pragma unroll 1
    for (int j = 0; j < NKC; j++) {
        __syncthreads();
        #pragma unroll
        for (int i = 0; i < 8; i++) {
            *(uint2*)(sm + offa[i]) = va[i];
            uint2 pb; pb.x = pack2(vb[i].x, vb[i].y); pb.y = pack2(vb[i].z, vb[i].w);
            *(uint2*)(sm + offb[i]) = pb;
        }
        __syncthreads();
        if (j + 1 < NKC) {
            #pragma unroll
            for (int i = 0; i < 8; i++) {
                va[i] = *(const uint2*)(asrc[i] + (j + 1) * 64);
                vb[i] = *(const float4*)(bsrc[i] + (j + 1) * 64);
            }
        }
        #pragma unroll
        for (int ks = 0; ks < 4; ks++) {
            uint32_t af[4][4], bf[2][4];
            #pragma unroll
            for (int mt = 0; mt < 4; mt++) {
                int row = wm * 64 + mt * 16 + (lane & 15);
                int byt = ks * 32 + ((lane >> 4) << 4);
                ldsm4(af[mt], sA + row * 128 + (byt ^ ((row & 7) << 4)));
            }
            #pragma unroll
            for (int n2 = 0; n2 < 2; n2++) {
                int row = wn * 32 + n2 * 16 + ((lane >> 4) << 3) + (lane & 7);
                int byt = ks * 32 + (((lane >> 3) & 1) << 4);
                ldsm4(bf[n2], sB + row * 128 + (byt ^ ((row & 7) << 4)));
            }
            #pragma unroll
            for (int mt = 0; mt < 4; mt++)
                #pragma unroll
                for (int nt = 0; nt < 4; nt++)
                    mma16816(acc[mt][nt], af[mt], &bf[nt >> 1][(nt & 1) * 2]);
        }
    }

    const int qrow = lane >> 2, qcol = (lane & 3) * 2;
    #pragma unroll
    for (int mt = 0; mt < 4; mt++) {
        int mbase = row0 + wm * 64 + mt * 16;
        #pragma unroll
        for (int nt = 0; nt < 4; nt++) {
            int dcol = d0 + wn * 32 + nt * 8 + qcol;
            int r0 = mbase + qrow, r1 = mbase + qrow + 8;
            if (r0 < nrows) {
                float2 v = make_float2(acc[mt][nt][0], acc[mt][nt][1]);
                *(float2*)&g_y[((size_t)e * CAP + r0) * DIM + dcol] = v;
            }
            if (r1 < nrows) {
                float2 v = make_float2(acc[mt][nt][2], acc[mt][nt][3]);
                *(float2*)&g_y[((size_t)e * CAP + r1) * DIM + dcol] = v;
            }
        }
    }
}

// ---------------- K5: weighted combine ---------------------------------------
__global__ __launch_bounds__(256) void k_combine(float* __restrict__ out) {
    const int t = blockIdx.x;
    const int tid = threadIdx.x;
    float4 acc0 = make_float4(0.f, 0.f, 0.f, 0.f);
    float4 acc1 = make_float4(0.f, 0.f, 0.f, 0.f);
    #pragma unroll
    for (int k = 0; k < TOPK; k++) {
        const int p = t * TOPK + k;
        const int e = g_eid[p];
        const int s = g_slot[p];
        if (s >= CAP) continue;
        const float sc = g_scr[p];
        const float4* yr = (const float4*)&g_y[((size_t)e * CAP + s) * DIM];
        float4 v0 = yr[tid];
        float4 v1 = yr[tid + 256];
        acc0.x += sc * v0.x; acc0.y += sc * v0.y; acc0.z += sc * v0.z; acc0.w += sc * v0.w;
        acc1.x += sc * v1.x; acc1.y += sc * v1.y; acc1.z += sc * v1.z; acc1.w += sc * v1.w;
    }
    float4* op = (float4*)(out + (size_t)t * DIM);
    op[tid] = acc0;
    op[tid + 256] = acc1;
}

// ---------------- launch -----------------------------------------------------
extern "C" void kernel_launch(void* const* d_in, const int* in_sizes, int n_in,
                              void* d_out, int out_size) {
    (void)in_sizes; (void)n_in; (void)out_size;
    const float* x      = (const float*)d_in[0];
    const float* gate_w = (const float*)d_in[1];
    const float* w_gate = (const float*)d_in[2];
    const float* w_up   = (const float*)d_in[3];
    const float* w_down = (const float*)d_in[4];
    float* out          = (float*)d_out;

    k_gate<<<NT / 4, 256>>>(x, gate_w);
    k_zero<<<1, 64>>>();
    k_route<<<NP / 256, 256>>>();
    k_gateup_mma<<<dim3(FFN_ / 64, CAP / 128, NE), 256>>>(x, w_gate, w_up);
    k_down_mma<<<dim3(DIM / 128, CAP / 128, NE), 256>>>(w_down);
    k_combine<<<NT, 256>>>(out);
}